// round 13
// baseline (speedup 1.0000x reference)
#include <cuda_runtime.h>
#include <cuda_bf16.h>
#include <math.h>

#define Bk   8
#define Cc   512
#define Wd   64
#define Hd   32
#define HIDd 256
#define Gg   1280
#define WH   (Wd*Hd)        // 2048
#define MXP  (Bk*WH)        // 16384
#define NDIAG (Wd + Hd - 1) // 95
#define NBLK 144            // 16 hid-chunks x 9 row-groups
#define RG   9

// ---- persistent-kernel smem layout (bytes) ----
#define WHI_OFF 0
#define WLO_OFF 81920
#define AHI_OFF 163840
#define ALO_OFF 196608
#define SMEM_P  229376

// ---- xp_tc smem layout (bytes): A 64x128B, B 128x128B, hi/lo each ----
#define XA_HI 0
#define XA_LO 8192
#define XB_HI 16384
#define XB_LO 32768
#define SMEM_X 49152

// ---------------- device scratch ----------------
__device__ float g_xp[(size_t)MXP * Gg];
__device__ float g_h [(size_t)WH * Bk * HIDd];      // (w,h,b,hid)
__device__ float g_c [(size_t)WH * Bk * HIDd];
__device__ float g_part[2 * 128 * HIDd];
__device__ float g_scale[HIDd];
__device__ float g_shift[HIDd];
__device__ unsigned g_cnt = 0;
__device__ unsigned g_gen = 0;

// ---------------- helpers ----------------
__device__ __forceinline__ unsigned pk(__nv_bfloat16 a, __nv_bfloat16 b) {
    __nv_bfloat162 t; t.x = a; t.y = b;
    return *(unsigned*)&t;
}
// XOR-swizzled frag load, 1024B row pitch (recurrence regions)
__device__ __forceinline__ unsigned ldfrag(const unsigned* base, int r, int k) {
    unsigned boff = ((unsigned)(k * 2)) ^ (((unsigned)r & 7u) << 4);
    return base[(r << 8) + (boff >> 2)];
}
// XOR-swizzled frag load, 128B row pitch (xp regions)
__device__ __forceinline__ unsigned ldfrag32(const unsigned* base, int r, int k) {
    unsigned boff = ((unsigned)(k * 2)) ^ (((unsigned)r & 7u) << 4);
    return base[(r << 5) + (boff >> 2)];
}
__device__ __forceinline__ void mma_bf16(float* d, unsigned a0, unsigned a1,
                                         unsigned a2, unsigned a3,
                                         unsigned b0, unsigned b1) {
    asm volatile(
        "mma.sync.aligned.m16n8k16.row.col.f32.bf16.bf16.f32 "
        "{%0,%1,%2,%3}, {%4,%5,%6,%7}, {%8,%9}, {%0,%1,%2,%3};"
        : "+f"(d[0]), "+f"(d[1]), "+f"(d[2]), "+f"(d[3])
        : "r"(a0), "r"(a1), "r"(a2), "r"(a3), "r"(b0), "r"(b1));
}
__device__ __forceinline__ void split_bf16(float f, __nv_bfloat16& h, __nv_bfloat16& l) {
    h = __float2bfloat16(f);
    l = __float2bfloat16(f - __bfloat162float(h));
}

// ---------------- Kernel A: xp = x @ Wx + b on HMMA (bf16 hi/lo split) ----------------
// grid (256 m-tiles of 64, 10 n-tiles of 128), 256 threads.
// 8 warps = 4 m-strips (16 rows) x 2 n-halves (64 cols). K=512 in 8 chunks of 64.
__global__ __launch_bounds__(256) void xp_tc(const float* __restrict__ x,
                                             const float* __restrict__ Wx,
                                             const float* __restrict__ bias) {
    extern __shared__ unsigned char smx[];
    const int tid = threadIdx.x;
    const int lane = tid & 31;
    const int wid  = tid >> 5;
    const int gid  = lane >> 2;
    const int tq   = lane & 3;

    const int m0 = blockIdx.x * 64;
    const int n0 = blockIdx.y * 128;
    const int b   = m0 >> 11;
    const int wh0 = m0 & 2047;

    const int wm = (wid & 3) * 16;     // m-strip
    const int nh = wid >> 2;           // n-half: tiles nh*8 .. nh*8+7

    const unsigned* AH = (const unsigned*)(smx + XA_HI);
    const unsigned* AL = (const unsigned*)(smx + XA_LO);
    const unsigned* BH = (const unsigned*)(smx + XB_HI);
    const unsigned* BL = (const unsigned*)(smx + XB_LO);

    float dd[8][4];
#pragma unroll
    for (int j = 0; j < 8; j++)
#pragma unroll
        for (int e = 0; e < 4; e++) dd[j][e] = 0.f;

    for (int c = 0; c < 8; c++) {
        const int k0 = c * 64;
        __syncthreads();   // previous chunk fully consumed

        // ---- stage A: 64 m x 64 k (k-row pairs, coalesced along m) ----
#pragma unroll
        for (int t = 0; t < 2; t++) {
            int q  = tid + t * 256;            // 0..511
            int kp = q >> 4;                   // 0..31 -> k = 2kp
            int mq = (q & 15) * 4;             // 0..60
            const float* xr = x + (size_t)(b * Cc + k0 + 2 * kp) * WH + wh0 + mq;
            float4 v0 = *(const float4*)xr;
            float4 v1 = *(const float4*)(xr + WH);
            float f0[4] = {v0.x, v0.y, v0.z, v0.w};
            float f1[4] = {v1.x, v1.y, v1.z, v1.w};
#pragma unroll
            for (int j = 0; j < 4; j++) {
                __nv_bfloat16 h0, l0, h1, l1;
                split_bf16(f0[j], h0, l0);
                split_bf16(f1[j], h1, l1);
                int r = mq + j;
                unsigned boff = ((unsigned)(4 * kp)) ^ (((unsigned)r & 7u) << 4);
                *(unsigned*)(smx + XA_HI + r * 128 + boff) = pk(h0, h1);
                *(unsigned*)(smx + XA_LO + r * 128 + boff) = pk(l0, l1);
            }
        }
        // ---- stage B: 128 n x 64 k ----
#pragma unroll
        for (int t = 0; t < 4; t++) {
            int q  = tid + t * 256;            // 0..1023
            int kp = q >> 5;                   // 0..31
            int nq = (q & 31) * 4;             // 0..124
            const float* wr = Wx + (size_t)(k0 + 2 * kp) * Gg + n0 + nq;
            float4 v0 = *(const float4*)wr;
            float4 v1 = *(const float4*)(wr + Gg);
            float f0[4] = {v0.x, v0.y, v0.z, v0.w};
            float f1[4] = {v1.x, v1.y, v1.z, v1.w};
#pragma unroll
            for (int j = 0; j < 4; j++) {
                __nv_bfloat16 h0, l0, h1, l1;
                split_bf16(f0[j], h0, l0);
                split_bf16(f1[j], h1, l1);
                int r = nq + j;
                unsigned boff = ((unsigned)(4 * kp)) ^ (((unsigned)r & 7u) << 4);
                *(unsigned*)(smx + XB_HI + r * 128 + boff) = pk(h0, h1);
                *(unsigned*)(smx + XB_LO + r * 128 + boff) = pk(l0, l1);
            }
        }
        __syncthreads();

        // ---- mma over this chunk: 4 k16 steps ----
        const int ra = wm + gid;
#pragma unroll
        for (int s = 0; s < 4; s++) {
            int ka = s * 16 + tq * 2;
            unsigned ah0 = ldfrag32(AH, ra,     ka);
            unsigned ah1 = ldfrag32(AH, ra + 8, ka);
            unsigned ah2 = ldfrag32(AH, ra,     ka + 8);
            unsigned ah3 = ldfrag32(AH, ra + 8, ka + 8);
            unsigned al0 = ldfrag32(AL, ra,     ka);
            unsigned al1 = ldfrag32(AL, ra + 8, ka);
            unsigned al2 = ldfrag32(AL, ra,     ka + 8);
            unsigned al3 = ldfrag32(AL, ra + 8, ka + 8);
#pragma unroll
            for (int j = 0; j < 8; j++) {
                int nr = (nh * 8 + j) * 8 + gid;
                unsigned bh0 = ldfrag32(BH, nr, ka);
                unsigned bh1 = ldfrag32(BH, nr, ka + 8);
                unsigned bl0 = ldfrag32(BL, nr, ka);
                unsigned bl1 = ldfrag32(BL, nr, ka + 8);
                mma_bf16(dd[j], ah0, ah1, ah2, ah3, bh0, bh1);
                mma_bf16(dd[j], ah0, ah1, ah2, ah3, bl0, bl1);
                mma_bf16(dd[j], al0, al1, al2, al3, bh0, bh1);
            }
        }
    }

    // ---- epilogue: bias + store ----
#pragma unroll
    for (int j = 0; j < 8; j++) {
        int col = n0 + (nh * 8 + j) * 8 + tq * 2;
        float b0 = bias[col];
        float b1 = bias[col + 1];
        int mA = m0 + wm + gid;
        int mB = mA + 8;
        *(float2*)&g_xp[(size_t)mA * Gg + col] = make_float2(dd[j][0] + b0, dd[j][1] + b1);
        *(float2*)&g_xp[(size_t)mB * Gg + col] = make_float2(dd[j][2] + b0, dd[j][3] + b1);
    }
}

// ---------------- grid-wide software barrier ----------------
__device__ __forceinline__ void gsync() {
    __threadfence();
    __syncthreads();
    if (threadIdx.x == 0) {
        unsigned old = *(volatile unsigned*)&g_gen;
        if (atomicAdd(&g_cnt, 1u) == NBLK - 1) {
            g_cnt = 0;
            __threadfence();
            *(volatile unsigned*)&g_gen = old + 1;
        } else {
            while (*(volatile unsigned*)&g_gen == old) { }
        }
        __threadfence();
    }
    __syncthreads();
}

// ---------------- persistent MD-LSTM recurrence on HMMA (proven R12) ----------------
__global__ __launch_bounds__(256, 1) void mdlstm_mma(const float* __restrict__ Wh1,
                                                     const float* __restrict__ Wh2) {
    extern __shared__ unsigned char smb[];
    __nv_bfloat16* WsHh = (__nv_bfloat16*)(smb + WHI_OFF);
    __nv_bfloat16* WsLh = (__nv_bfloat16*)(smb + WLO_OFF);

    const int tid = threadIdx.x;
    const int bid = blockIdx.x;
    const int nb  = bid & 15;
    const int rg  = bid >> 4;

    for (int i = tid; i < 80 * 512; i += 256) {
        int c = i >> 9, k = i & 511;
        int gc = (c >> 4) * 256 + nb * 16 + (c & 15);
        float w = (k < 256) ? Wh1[(size_t)k * Gg + gc]
                            : Wh2[(size_t)(k - 256) * Gg + gc];
        __nv_bfloat16 h = __float2bfloat16(w);
        __nv_bfloat16 l = __float2bfloat16(w - __bfloat162float(h));
        unsigned boff = ((unsigned)(k * 2)) ^ (((unsigned)c & 7u) << 4);
        WsHh[c * 512 + (boff >> 1)] = h;
        WsLh[c * 512 + (boff >> 1)] = l;
    }

    const int lane = tid & 31;
    const int wid  = tid >> 5;
    const int gid  = lane >> 2;
    const int tq   = lane & 3;
    const int wm   = (wid & 1) * 16;
    const int wg   = wid >> 1;
    const int srow = tid >> 3;
    const int sq   = tid & 7;

    const unsigned* AH = (const unsigned*)(smb + AHI_OFF);
    const unsigned* AL = (const unsigned*)(smb + ALO_OFF);
    const unsigned* BH = (const unsigned*)(smb + WHI_OFF);
    const unsigned* BL = (const unsigned*)(smb + WLO_OFF);

    for (int d = 0; d < NDIAG; d++) {
        int w_lo = d - (Hd - 1); if (w_lo < 0) w_lo = 0;
        int w_hi = (d < Wd - 1) ? d : (Wd - 1);
        int M = (w_hi - w_lo + 1) * Bk;
        int mt2 = (M + RG - 1) / RG;
        int r0 = rg * mt2;

        if (r0 < M) {
            {
                const float* pl = nullptr;
                const float* pu = nullptr;
                int gr = r0 + srow;
                if (srow < mt2 && gr < M) {
                    int ci = gr >> 3, b = gr & 7;
                    int w = w_lo + ci, h = d - w;
                    if (h > 0) pl = g_h + ((size_t)((w * Hd + (h - 1)) * Bk + b)) * HIDd;
                    if (w > 0) pu = g_h + ((size_t)(((w - 1) * Hd + h) * Bk + b)) * HIDd;
                }
#pragma unroll
                for (int j = 0; j < 8; j++) {
                    int kk = (sq + 8 * j) * 8;
                    const float* src = (j < 4) ? pl : pu;
                    float4 v0 = make_float4(0.f, 0.f, 0.f, 0.f);
                    float4 v1 = v0;
                    if (src) {
                        int ko = (j < 4) ? kk : kk - 256;
                        v0 = *(const float4*)(src + ko);
                        v1 = *(const float4*)(src + ko + 4);
                    }
                    float f[8] = {v0.x, v0.y, v0.z, v0.w, v1.x, v1.y, v1.z, v1.w};
                    __nv_bfloat16 hh[8], ll[8];
#pragma unroll
                    for (int e = 0; e < 8; e++) split_bf16(f[e], hh[e], ll[e]);
                    uint4 Hv, Lv;
                    Hv.x = pk(hh[0], hh[1]); Hv.y = pk(hh[2], hh[3]);
                    Hv.z = pk(hh[4], hh[5]); Hv.w = pk(hh[6], hh[7]);
                    Lv.x = pk(ll[0], ll[1]); Lv.y = pk(ll[2], ll[3]);
                    Lv.z = pk(ll[4], ll[5]); Lv.w = pk(ll[6], ll[7]);
                    unsigned boff = ((unsigned)(kk * 2)) ^ (((unsigned)srow & 7u) << 4);
                    *(uint4*)(smb + AHI_OFF + srow * 1024 + boff) = Hv;
                    *(uint4*)(smb + ALO_OFF + srow * 1024 + boff) = Lv;
                }
            }
            __syncthreads();

            int nts[3]; int nn = 0;
            for (int t = wg; t < 10; t += 4) nts[nn++] = t;
            float dd[3][4];
#pragma unroll
            for (int j = 0; j < 3; j++)
#pragma unroll
                for (int e = 0; e < 4; e++) dd[j][e] = 0.f;

            const int ra = wm + gid;
#pragma unroll 2
            for (int k0 = 0; k0 < 512; k0 += 16) {
                int ka = k0 + tq * 2;
                unsigned ah0 = ldfrag(AH, ra,     ka);
                unsigned ah1 = ldfrag(AH, ra + 8, ka);
                unsigned ah2 = ldfrag(AH, ra,     ka + 8);
                unsigned ah3 = ldfrag(AH, ra + 8, ka + 8);
                unsigned al0 = ldfrag(AL, ra,     ka);
                unsigned al1 = ldfrag(AL, ra + 8, ka);
                unsigned al2 = ldfrag(AL, ra,     ka + 8);
                unsigned al3 = ldfrag(AL, ra + 8, ka + 8);
                for (int j = 0; j < nn; j++) {
                    int nr = nts[j] * 8 + gid;
                    unsigned bh0 = ldfrag(BH, nr, ka);
                    unsigned bh1 = ldfrag(BH, nr, ka + 8);
                    unsigned bl0 = ldfrag(BL, nr, ka);
                    unsigned bl1 = ldfrag(BL, nr, ka + 8);
                    mma_bf16(dd[j], ah0, ah1, ah2, ah3, bh0, bh1);
                    mma_bf16(dd[j], ah0, ah1, ah2, ah3, bl0, bl1);
                    mma_bf16(dd[j], al0, al1, al2, al3, bh0, bh1);
                }
            }

            __syncthreads();
            float* Gs = (float*)(smb + AHI_OFF);   // [32][84]
            for (int j = 0; j < nn; j++) {
                int c0 = nts[j] * 8 + tq * 2;
                *(float2*)&Gs[(wm + gid) * 84 + c0]     = make_float2(dd[j][0], dd[j][1]);
                *(float2*)&Gs[(wm + gid + 8) * 84 + c0] = make_float2(dd[j][2], dd[j][3]);
            }
            __syncthreads();

#pragma unroll
            for (int pass = 0; pass < 2; pass++) {
                int r = (tid >> 4) + pass * 16;
                int hidx = tid & 15;
                if (r < mt2) {
                    int gr = r0 + r;
                    if (gr < M) {
                        int ci = gr >> 3, b = gr & 7;
                        int w = w_lo + ci, h = d - w;
                        const int hid = nb * 16 + hidx;

                        const float* xg = g_xp + ((size_t)(b * WH + w * Hd + h)) * Gg;
                        float gi  = Gs[r * 84 +   0 + hidx] + xg[hid];
                        float gf1 = Gs[r * 84 +  16 + hidx] + xg[HIDd + hid];
                        float gf2 = Gs[r * 84 +  32 + hidx] + xg[2 * HIDd + hid];
                        float go  = Gs[r * 84 +  48 + hidx] + xg[3 * HIDd + hid];
                        float gc  = Gs[r * 84 +  64 + hidx] + xg[4 * HIDd + hid];

                        float i_ = 1.f / (1.f + expf(-gi));
                        float f1 = 1.f / (1.f + expf(-gf1));
                        float f2 = 1.f / (1.f + expf(-gf2));
                        float o_ = 1.f / (1.f + expf(-go));
                        float cand = tanhf(gc);

                        float cl = (h > 0) ? g_c[((size_t)((w * Hd + (h - 1)) * Bk + b)) * HIDd + hid] : 0.f;
                        float cu = (w > 0) ? g_c[((size_t)(((w - 1) * Hd + h) * Bk + b)) * HIDd + hid] : 0.f;

                        float cc = i_ * cand + f1 * cl + f2 * cu;
                        float hv = o_ * tanhf(cc);

                        size_t oidx = ((size_t)((w * Hd + h) * Bk + b)) * HIDd + hid;
                        g_c[oidx] = cc;
                        g_h[oidx] = hv;
                    }
                }
            }
        }

        gsync();
    }
}

// ---------------- BN stats ----------------
__global__ __launch_bounds__(256) void bn_reduce1() {
    const int t = threadIdx.x;
    const size_t r0 = (size_t)blockIdx.x * 128;
    float s = 0.f, s2 = 0.f;
    for (int r = 0; r < 128; r++) {
        float v = g_h[(r0 + r) * HIDd + t];
        s += v;
        s2 += v * v;
    }
    g_part[blockIdx.x * HIDd + t] = s;
    g_part[128 * HIDd + blockIdx.x * HIDd + t] = s2;
}

__global__ __launch_bounds__(256) void bn_reduce2(const float* __restrict__ gamma,
                                                  const float* __restrict__ beta) {
    const int t = threadIdx.x;
    float s0 = 0.f, s1 = 0.f, q0 = 0.f, q1 = 0.f;
#pragma unroll 4
    for (int i = 0; i < 128; i += 2) {
        s0 += g_part[i * HIDd + t];
        s1 += g_part[(i + 1) * HIDd + t];
        q0 += g_part[128 * HIDd + i * HIDd + t];
        q1 += g_part[128 * HIDd + (i + 1) * HIDd + t];
    }
    float s = s0 + s1, s2 = q0 + q1;
    const float invn = 1.f / (float)MXP;
    float mean = s * invn;
    float var  = s2 * invn - mean * mean;
    float sc   = gamma[t] * rsqrtf(var + 1e-5f);
    g_scale[t] = sc;
    g_shift[t] = beta[t] - mean * sc;
}

// ---------------- final writeout ----------------
__global__ __launch_bounds__(256) void writeout(float* __restrict__ out) {
    __shared__ float t[32][257];
    const int bw = blockIdx.x;
    const int b  = bw >> 6;
    const int w  = bw & 63;
    const int tid = threadIdx.x;
    const int ch8 = tid >> 5;
    const int hl  = tid & 31;

    for (int hh = 0; hh < 32; hh++)
        t[hh][tid] = g_h[((size_t)((w * Hd + hh) * Bk + b)) * HIDd + tid];
    __syncthreads();
    for (int c0 = 0; c0 < 256; c0 += 8) {
        int ch = c0 + ch8;
        float v = t[hl][ch];
        size_t oi = (((size_t)b * HIDd + ch) * Wd + w) * Hd + hl;
        out[oi] = tanhf(v * g_scale[ch] + g_shift[ch]);
        out[(size_t)MXP * HIDd + oi] = v;
    }
    __syncthreads();

    for (int hh = 0; hh < 32; hh++)
        t[hh][tid] = g_c[((size_t)((w * Hd + hh) * Bk + b)) * HIDd + tid];
    __syncthreads();
    for (int c0 = 0; c0 < 256; c0 += 8) {
        int ch = c0 + ch8;
        size_t oi = (((size_t)b * HIDd + ch) * Wd + w) * Hd + hl;
        out[(size_t)2 * MXP * HIDd + oi] = t[hl][ch];
    }
}

// ---------------- launch ----------------
extern "C" void kernel_launch(void* const* d_in, const int* in_sizes, int n_in,
                              void* d_out, int out_size) {
    const float* x     = (const float*)d_in[0];
    const float* Wx    = (const float*)d_in[1];
    const float* Wh1   = (const float*)d_in[2];
    const float* Wh2   = (const float*)d_in[3];
    const float* bias  = (const float*)d_in[4];
    const float* gamma = (const float*)d_in[5];
    const float* beta  = (const float*)d_in[6];
    float* out = (float*)d_out;

    cudaFuncSetAttribute(xp_tc,
                         cudaFuncAttributeMaxDynamicSharedMemorySize, SMEM_X);
    cudaFuncSetAttribute(mdlstm_mma,
                         cudaFuncAttributeMaxDynamicSharedMemorySize, SMEM_P);

    xp_tc<<<dim3(MXP / 64, Gg / 128), 256, SMEM_X>>>(x, Wx, bias);
    mdlstm_mma<<<NBLK, 256, SMEM_P>>>(Wh1, Wh2);
    bn_reduce1<<<128, 256>>>();
    bn_reduce2<<<1, 256>>>(gamma, beta);
    writeout<<<Bk * Wd, 256>>>(out);
}

// round 16
// speedup vs baseline: 1.1089x; 1.1089x over previous
#include <cuda_runtime.h>
#include <cuda_bf16.h>
#include <math.h>

#define Bk   8
#define Cc   512
#define Wd   64
#define Hd   32
#define HIDd 256
#define Gg   1280
#define WH   (Wd*Hd)        // 2048
#define MXP  (Bk*WH)        // 16384
#define NDIAG (Wd + Hd - 1) // 95
#define NBLK 144
#define RG   9

// ---- persistent-kernel smem layout (bytes) ----
#define WHI_OFF 0
#define WLO_OFF 81920
#define AHI_OFF 163840
#define ALO_OFF 196608
#define SMEM_P  229376

// ---- xp_tc smem layout (bytes): A 64x128B, B 128x128B, hi/lo each ----
#define XA_HI 0
#define XA_LO 8192
#define XB_HI 16384
#define XB_LO 32768
#define SMEM_X 49152

// ---------------- device scratch ----------------
__device__ float g_xp[(size_t)MXP * Gg];
__device__ float g_h [(size_t)WH * Bk * HIDd];
__device__ float g_c [(size_t)WH * Bk * HIDd];
__device__ unsigned g_hh2[(size_t)WH * Bk * 128];   // h as bf16-hi k-pairs
__device__ unsigned g_hl2[(size_t)WH * Bk * 128];   // h as bf16-lo k-pairs
__device__ unsigned g_x2h[(size_t)Bk * 256 * WH];   // x packed [b][kp][wh]
__device__ unsigned g_x2l[(size_t)Bk * 256 * WH];
__device__ unsigned g_w2h[1280 * 256];              // Wx packed [n][kp]
__device__ unsigned g_w2l[1280 * 256];
__device__ float g_part[2 * 64 * HIDd];
__device__ float g_scale[HIDd];
__device__ float g_shift[HIDd];
__device__ unsigned g_cnt = 0;
__device__ unsigned g_gen = 0;

// ---------------- helpers ----------------
__device__ __forceinline__ unsigned pk(__nv_bfloat16 a, __nv_bfloat16 b) {
    __nv_bfloat162 t; t.x = a; t.y = b;
    return *(unsigned*)&t;
}
__device__ __forceinline__ void split_bf16(float f, __nv_bfloat16& h, __nv_bfloat16& l) {
    h = __float2bfloat16(f);
    l = __float2bfloat16(f - __bfloat162float(h));
}
// XOR-swizzled frag load, 1024B row pitch (recurrence)
__device__ __forceinline__ unsigned ldfrag(const unsigned* base, int r, int k) {
    unsigned boff = ((unsigned)(k * 2)) ^ (((unsigned)r & 7u) << 4);
    return base[(r << 8) + (boff >> 2)];
}
// XOR-swizzled frag load, 128B row pitch (xp)
__device__ __forceinline__ unsigned ldfrag32(const unsigned* base, int r, int k) {
    unsigned boff = ((unsigned)(k * 2)) ^ (((unsigned)r & 7u) << 4);
    return base[(r << 5) + (boff >> 2)];
}
__device__ __forceinline__ void mma_bf16(float* d, unsigned a0, unsigned a1,
                                         unsigned a2, unsigned a3,
                                         unsigned b0, unsigned b1) {
    asm volatile(
        "mma.sync.aligned.m16n8k16.row.col.f32.bf16.bf16.f32 "
        "{%0,%1,%2,%3}, {%4,%5,%6,%7}, {%8,%9}, {%0,%1,%2,%3};"
        : "+f"(d[0]), "+f"(d[1]), "+f"(d[2]), "+f"(d[3])
        : "r"(a0), "r"(a1), "r"(a2), "r"(a3), "r"(b0), "r"(b1));
}

// ---------------- pre-pack kernels ----------------
__global__ __launch_bounds__(256) void cvt_x(const float* __restrict__ x) {
    size_t i = (size_t)blockIdx.x * 256 + threadIdx.x;   // over Bk*256*WH
    int wh = (int)(i & 2047);
    int kp = (int)((i >> 11) & 255);
    int b  = (int)(i >> 19);
    float f0 = x[((size_t)b * Cc + 2 * kp) * WH + wh];
    float f1 = x[((size_t)b * Cc + 2 * kp + 1) * WH + wh];
    __nv_bfloat16 h0, l0, h1, l1;
    split_bf16(f0, h0, l0);
    split_bf16(f1, h1, l1);
    g_x2h[i] = pk(h0, h1);
    g_x2l[i] = pk(l0, l1);
}

__global__ __launch_bounds__(256) void cvt_w(const float* __restrict__ Wx) {
    int i = blockIdx.x * 256 + threadIdx.x;   // over 256*1280, n fastest
    int n  = i % 1280;
    int kp = i / 1280;
    float f0 = Wx[(size_t)(2 * kp) * Gg + n];
    float f1 = Wx[(size_t)(2 * kp + 1) * Gg + n];
    __nv_bfloat16 h0, l0, h1, l1;
    split_bf16(f0, h0, l0);
    split_bf16(f1, h1, l1);
    g_w2h[n * 256 + kp] = pk(h0, h1);
    g_w2l[n * 256 + kp] = pk(l0, l1);
}

// ---------------- Kernel A: xp = x @ Wx + b on HMMA (pre-packed bf16) ----------------
// grid (256 m-tiles of 64, 10 n-tiles of 128), 256 threads.
__global__ __launch_bounds__(256) void xp_tc(const float* __restrict__ bias) {
    extern __shared__ unsigned char smx[];
    const int tid = threadIdx.x;
    const int lane = tid & 31;
    const int wid  = tid >> 5;
    const int gid  = lane >> 2;
    const int tq   = lane & 3;

    const int m0 = blockIdx.x * 64;
    const int n0 = blockIdx.y * 128;
    const int b   = m0 >> 11;
    const int wh0 = m0 & 2047;

    const int wm = (wid & 3) * 16;
    const int nh = wid >> 2;

    const unsigned* AH = (const unsigned*)(smx + XA_HI);
    const unsigned* AL = (const unsigned*)(smx + XA_LO);
    const unsigned* BH = (const unsigned*)(smx + XB_HI);
    const unsigned* BL = (const unsigned*)(smx + XB_LO);

    // staging maps
    const int a_kpl = tid >> 3;          // 0..31
    const int a_m4  = (tid & 7) * 8;     // 0..56
    const int b_n   = tid >> 1;          // 0..127
    const int b_hf  = tid & 1;           // half of 32 kp

    float dd[8][4];
#pragma unroll
    for (int j = 0; j < 8; j++)
#pragma unroll
        for (int e = 0; e < 4; e++) dd[j][e] = 0.f;

    for (int c = 0; c < 8; c++) {
        __syncthreads();

        // ---- stage A: pure copies ----
        {
            const unsigned* sh = g_x2h + ((size_t)(b * 256 + c * 32 + a_kpl)) * WH + wh0 + a_m4;
            const unsigned* sl = g_x2l + ((size_t)(b * 256 + c * 32 + a_kpl)) * WH + wh0 + a_m4;
            uint4 h0 = *(const uint4*)sh;
            uint4 h1 = *(const uint4*)(sh + 4);
            uint4 l0 = *(const uint4*)sl;
            uint4 l1 = *(const uint4*)(sl + 4);
            unsigned hv[8] = {h0.x, h0.y, h0.z, h0.w, h1.x, h1.y, h1.z, h1.w};
            unsigned lv[8] = {l0.x, l0.y, l0.z, l0.w, l1.x, l1.y, l1.z, l1.w};
#pragma unroll
            for (int e = 0; e < 8; e++) {
                int r = a_m4 + e;
                unsigned boff = ((unsigned)(4 * a_kpl)) ^ (((unsigned)r & 7u) << 4);
                *(unsigned*)(smx + XA_HI + r * 128 + boff) = hv[e];
                *(unsigned*)(smx + XA_LO + r * 128 + boff) = lv[e];
            }
        }
        // ---- stage B: pure copies ----
        {
            const unsigned* sh = g_w2h + (size_t)(n0 + b_n) * 256 + c * 32 + b_hf * 16;
            const unsigned* sl = g_w2l + (size_t)(n0 + b_n) * 256 + c * 32 + b_hf * 16;
#pragma unroll
            for (int q = 0; q < 4; q++) {
                uint4 hq = *(const uint4*)(sh + q * 4);
                uint4 lq = *(const uint4*)(sl + q * 4);
                unsigned hv[4] = {hq.x, hq.y, hq.z, hq.w};
                unsigned lv[4] = {lq.x, lq.y, lq.z, lq.w};
#pragma unroll
                for (int e = 0; e < 4; e++) {
                    int kpl = b_hf * 16 + q * 4 + e;
                    unsigned boff = ((unsigned)(4 * kpl)) ^ (((unsigned)b_n & 7u) << 4);
                    *(unsigned*)(smx + XB_HI + b_n * 128 + boff) = hv[e];
                    *(unsigned*)(smx + XB_LO + b_n * 128 + boff) = lv[e];
                }
            }
        }
        __syncthreads();

        // ---- mma: 4 k16 steps ----
        const int ra = wm + gid;
#pragma unroll
        for (int s = 0; s < 4; s++) {
            int ka = s * 16 + tq * 2;
            unsigned ah0 = ldfrag32(AH, ra,     ka);
            unsigned ah1 = ldfrag32(AH, ra + 8, ka);
            unsigned ah2 = ldfrag32(AH, ra,     ka + 8);
            unsigned ah3 = ldfrag32(AH, ra + 8, ka + 8);
            unsigned al0 = ldfrag32(AL, ra,     ka);
            unsigned al1 = ldfrag32(AL, ra + 8, ka);
            unsigned al2 = ldfrag32(AL, ra,     ka + 8);
            unsigned al3 = ldfrag32(AL, ra + 8, ka + 8);
#pragma unroll
            for (int j = 0; j < 8; j++) {
                int nr = (nh * 8 + j) * 8 + gid;
                unsigned bh0 = ldfrag32(BH, nr, ka);
                unsigned bh1 = ldfrag32(BH, nr, ka + 8);
                unsigned bl0 = ldfrag32(BL, nr, ka);
                unsigned bl1 = ldfrag32(BL, nr, ka + 8);
                mma_bf16(dd[j], ah0, ah1, ah2, ah3, bh0, bh1);
                mma_bf16(dd[j], ah0, ah1, ah2, ah3, bl0, bl1);
                mma_bf16(dd[j], al0, al1, al2, al3, bh0, bh1);
            }
        }
    }

#pragma unroll
    for (int j = 0; j < 8; j++) {
        int col = n0 + (nh * 8 + j) * 8 + tq * 2;
        float b0 = bias[col];
        float b1 = bias[col + 1];
        int mA = m0 + wm + gid;
        int mB = mA + 8;
        *(float2*)&g_xp[(size_t)mA * Gg + col] = make_float2(dd[j][0] + b0, dd[j][1] + b1);
        *(float2*)&g_xp[(size_t)mB * Gg + col] = make_float2(dd[j][2] + b0, dd[j][3] + b1);
    }
}

// ---------------- grid-wide software barrier ----------------
__device__ __forceinline__ void gsync() {
    __threadfence();
    __syncthreads();
    if (threadIdx.x == 0) {
        unsigned old = *(volatile unsigned*)&g_gen;
        if (atomicAdd(&g_cnt, 1u) == NBLK - 1) {
            g_cnt = 0;
            __threadfence();
            *(volatile unsigned*)&g_gen = old + 1;
        } else {
            while (*(volatile unsigned*)&g_gen == old) { }
        }
        __threadfence();
    }
    __syncthreads();
}

// ---------------- persistent MD-LSTM recurrence on HMMA ----------------
__global__ __launch_bounds__(256, 1) void mdlstm_mma(const float* __restrict__ Wh1,
                                                     const float* __restrict__ Wh2) {
    extern __shared__ unsigned char smb[];
    __nv_bfloat16* WsHh = (__nv_bfloat16*)(smb + WHI_OFF);
    __nv_bfloat16* WsLh = (__nv_bfloat16*)(smb + WLO_OFF);

    const int tid = threadIdx.x;
    const int bid = blockIdx.x;
    const int nb  = bid & 15;
    const int rg  = bid >> 4;

    // one-time weight preload (cvt here is fine: once per session)
    for (int i = tid; i < 80 * 512; i += 256) {
        int c = i >> 9, k = i & 511;
        int gc = (c >> 4) * 256 + nb * 16 + (c & 15);
        float w = (k < 256) ? Wh1[(size_t)k * Gg + gc]
                            : Wh2[(size_t)(k - 256) * Gg + gc];
        __nv_bfloat16 h, l;
        split_bf16(w, h, l);
        unsigned boff = ((unsigned)(k * 2)) ^ (((unsigned)c & 7u) << 4);
        WsHh[c * 512 + (boff >> 1)] = h;
        WsLh[c * 512 + (boff >> 1)] = l;
    }

    const int lane = tid & 31;
    const int wid  = tid >> 5;
    const int gid  = lane >> 2;
    const int tq   = lane & 3;
    const int wm   = (wid & 1) * 16;
    const int wg   = wid >> 1;
    const int srow = tid >> 3;
    const int sq   = tid & 7;

    const unsigned* AH = (const unsigned*)(smb + AHI_OFF);
    const unsigned* AL = (const unsigned*)(smb + ALO_OFF);
    const unsigned* BH = (const unsigned*)(smb + WHI_OFF);
    const unsigned* BL = (const unsigned*)(smb + WLO_OFF);

    for (int d = 0; d < NDIAG; d++) {
        int w_lo = d - (Hd - 1); if (w_lo < 0) w_lo = 0;
        int w_hi = (d < Wd - 1) ? d : (Wd - 1);
        int M = (w_hi - w_lo + 1) * Bk;
        int mt2 = (M + RG - 1) / RG;
        int r0 = rg * mt2;

        if (r0 < M) {
            // ---- stage A from pre-packed bf16 h (pure copies) ----
            {
                const unsigned* plh = nullptr; const unsigned* pll = nullptr;
                const unsigned* puh = nullptr; const unsigned* pul = nullptr;
                int gr = r0 + srow;
                if (srow < mt2 && gr < M) {
                    int ci = gr >> 3, b = gr & 7;
                    int w = w_lo + ci, h = d - w;
                    if (h > 0) {
                        size_t cell = (size_t)((w * Hd + (h - 1)) * Bk + b);
                        plh = g_hh2 + cell * 128;
                        pll = g_hl2 + cell * 128;
                    }
                    if (w > 0) {
                        size_t cell = (size_t)(((w - 1) * Hd + h) * Bk + b);
                        puh = g_hh2 + cell * 128;
                        pul = g_hl2 + cell * 128;
                    }
                }
#pragma unroll
                for (int j = 0; j < 8; j++) {
                    int kk = (sq + 8 * j) * 8;
                    uint4 Hv = make_uint4(0, 0, 0, 0);
                    uint4 Lv = make_uint4(0, 0, 0, 0);
                    if (j < 4) {
                        if (plh) { int kp0 = kk >> 1;
                            Hv = *(const uint4*)(plh + kp0);
                            Lv = *(const uint4*)(pll + kp0); }
                    } else {
                        if (puh) { int kp0 = (kk - 256) >> 1;
                            Hv = *(const uint4*)(puh + kp0);
                            Lv = *(const uint4*)(pul + kp0); }
                    }
                    unsigned boff = ((unsigned)(kk * 2)) ^ (((unsigned)srow & 7u) << 4);
                    *(uint4*)(smb + AHI_OFF + srow * 1024 + boff) = Hv;
                    *(uint4*)(smb + ALO_OFF + srow * 1024 + boff) = Lv;
                }
            }
            __syncthreads();

            int nts[3]; int nn = 0;
            for (int t = wg; t < 10; t += 4) nts[nn++] = t;
            float dd[3][4];
#pragma unroll
            for (int j = 0; j < 3; j++)
#pragma unroll
                for (int e = 0; e < 4; e++) dd[j][e] = 0.f;

            const int ra = wm + gid;
#pragma unroll 2
            for (int k0 = 0; k0 < 512; k0 += 16) {
                int ka = k0 + tq * 2;
                unsigned ah0 = ldfrag(AH, ra,     ka);
                unsigned ah1 = ldfrag(AH, ra + 8, ka);
                unsigned ah2 = ldfrag(AH, ra,     ka + 8);
                unsigned ah3 = ldfrag(AH, ra + 8, ka + 8);
                unsigned al0 = ldfrag(AL, ra,     ka);
                unsigned al1 = ldfrag(AL, ra + 8, ka);
                unsigned al2 = ldfrag(AL, ra,     ka + 8);
                unsigned al3 = ldfrag(AL, ra + 8, ka + 8);
                for (int j = 0; j < nn; j++) {
                    int nr = nts[j] * 8 + gid;
                    unsigned bh0 = ldfrag(BH, nr, ka);
                    unsigned bh1 = ldfrag(BH, nr, ka + 8);
                    unsigned bl0 = ldfrag(BL, nr, ka);
                    unsigned bl1 = ldfrag(BL, nr, ka + 8);
                    mma_bf16(dd[j], ah0, ah1, ah2, ah3, bh0, bh1);
                    mma_bf16(dd[j], ah0, ah1, ah2, ah3, bl0, bl1);
                    mma_bf16(dd[j], al0, al1, al2, al3, bh0, bh1);
                }
            }

            __syncthreads();
            float* Gs = (float*)(smb + AHI_OFF);   // [32][84]
            for (int j = 0; j < nn; j++) {
                int c0 = nts[j] * 8 + tq * 2;
                *(float2*)&Gs[(wm + gid) * 84 + c0]     = make_float2(dd[j][0], dd[j][1]);
                *(float2*)&Gs[(wm + gid + 8) * 84 + c0] = make_float2(dd[j][2], dd[j][3]);
            }
            __syncthreads();

            // ---- fused LSTM pointwise + bf16 h pair emit ----
#pragma unroll
            for (int pass = 0; pass < 2; pass++) {
                int r = (tid >> 4) + pass * 16;
                int hidx = tid & 15;
                float hv = 0.f;
                bool valid = false;
                int w = 0, h = 0, b = 0;
                if (r < mt2) {
                    int gr = r0 + r;
                    if (gr < M) {
                        int ci = gr >> 3; b = gr & 7;
                        w = w_lo + ci; h = d - w;
                        valid = true;
                        const int hid = nb * 16 + hidx;

                        const float* xg = g_xp + ((size_t)(b * WH + w * Hd + h)) * Gg;
                        float gi  = Gs[r * 84 +   0 + hidx] + xg[hid];
                        float gf1 = Gs[r * 84 +  16 + hidx] + xg[HIDd + hid];
                        float gf2 = Gs[r * 84 +  32 + hidx] + xg[2 * HIDd + hid];
                        float go  = Gs[r * 84 +  48 + hidx] + xg[3 * HIDd + hid];
                        float gc  = Gs[r * 84 +  64 + hidx] + xg[4 * HIDd + hid];

                        float i_ = 1.f / (1.f + expf(-gi));
                        float f1 = 1.f / (1.f + expf(-gf1));
                        float f2 = 1.f / (1.f + expf(-gf2));
                        float o_ = 1.f / (1.f + expf(-go));
                        float cand = tanhf(gc);

                        float cl = (h > 0) ? g_c[((size_t)((w * Hd + (h - 1)) * Bk + b)) * HIDd + hid] : 0.f;
                        float cu = (w > 0) ? g_c[((size_t)(((w - 1) * Hd + h) * Bk + b)) * HIDd + hid] : 0.f;

                        float cc = i_ * cand + f1 * cl + f2 * cu;
                        hv = o_ * tanhf(cc);

                        size_t oidx = ((size_t)((w * Hd + h) * Bk + b)) * HIDd + hid;
                        g_c[oidx] = cc;
                        g_h[oidx] = hv;
                    }
                }
                // warp-uniform shfl (odd lane of a pair shares r with even lane)
                float hv_n = __shfl_down_sync(0xffffffffu, hv, 1);
                if (valid && !(hidx & 1)) {
                    __nv_bfloat16 h0, l0, h1, l1;
                    split_bf16(hv, h0, l0);
                    split_bf16(hv_n, h1, l1);
                    size_t cell = (size_t)((w * Hd + h) * Bk + b);
                    int kp = nb * 8 + (hidx >> 1);
                    g_hh2[cell * 128 + kp] = pk(h0, h1);
                    g_hl2[cell * 128 + kp] = pk(l0, l1);
                }
            }
        }

        gsync();
    }
}

// ---------------- BN stats ----------------
__global__ __launch_bounds__(256) void bn_reduce1() {
    const int t = threadIdx.x;
    const size_t r0 = (size_t)blockIdx.x * 256;
    float s = 0.f, s2 = 0.f;
    for (int r = 0; r < 256; r++) {
        float v = g_h[(r0 + r) * HIDd + t];
        s += v;
        s2 += v * v;
    }
    g_part[blockIdx.x * HIDd + t] = s;
    g_part[64 * HIDd + blockIdx.x * HIDd + t] = s2;
}

__global__ __launch_bounds__(256) void bn_reduce2(const float* __restrict__ gamma,
                                                  const float* __restrict__ beta) {
    const int t = threadIdx.x;
    float s0 = 0.f, s1 = 0.f, q0 = 0.f, q1 = 0.f;
#pragma unroll 4
    for (int i = 0; i < 64; i += 2) {
        s0 += g_part[i * HIDd + t];
        s1 += g_part[(i + 1) * HIDd + t];
        q0 += g_part[64 * HIDd + i * HIDd + t];
        q1 += g_part[64 * HIDd + (i + 1) * HIDd + t];
    }
    float s = s0 + s1, s2 = q0 + q1;
    const float invn = 1.f / (float)MXP;
    float mean = s * invn;
    float var  = s2 * invn - mean * mean;
    float sc   = gamma[t] * rsqrtf(var + 1e-5f);
    g_scale[t] = sc;
    g_shift[t] = beta[t] - mean * sc;
}

// ---------------- final writeout ----------------
__global__ __launch_bounds__(256) void writeout(float* __restrict__ out) {
    __shared__ float t[32][257];
    const int bw = blockIdx.x;
    const int b  = bw >> 6;
    const int w  = bw & 63;
    const int tid = threadIdx.x;
    const int ch8 = tid >> 5;
    const int hl  = tid & 31;

    for (int hh = 0; hh < 32; hh++)
        t[hh][tid] = g_h[((size_t)((w * Hd + hh) * Bk + b)) * HIDd + tid];
    __syncthreads();
    for (int c0 = 0; c0 < 256; c0 += 8) {
        int ch = c0 + ch8;
        float v = t[hl][ch];
        size_t oi = (((size_t)b * HIDd + ch) * Wd + w) * Hd + hl;
        out[oi] = tanhf(v * g_scale[ch] + g_shift[ch]);
        out[(size_t)MXP * HIDd + oi] = v;
    }
    __syncthreads();

    for (int hh = 0; hh < 32; hh++)
        t[hh][tid] = g_c[((size_t)((w * Hd + hh) * Bk + b)) * HIDd + tid];
    __syncthreads();
    for (int c0 = 0; c0 < 256; c0 += 8) {
        int ch = c0 + ch8;
        size_t oi = (((size_t)b * HIDd + ch) * Wd + w) * Hd + hl;
        out[(size_t)2 * MXP * HIDd + oi] = t[hl][ch];
    }
}

// ---------------- launch ----------------
extern "C" void kernel_launch(void* const* d_in, const int* in_sizes, int n_in,
                              void* d_out, int out_size) {
    const float* x     = (const float*)d_in[0];
    const float* Wx    = (const float*)d_in[1];
    const float* Wh1   = (const float*)d_in[2];
    const float* Wh2   = (const float*)d_in[3];
    const float* bias  = (const float*)d_in[4];
    const float* gamma = (const float*)d_in[5];
    const float* beta  = (const float*)d_in[6];
    float* out = (float*)d_out;

    cudaFuncSetAttribute(xp_tc,
                         cudaFuncAttributeMaxDynamicSharedMemorySize, SMEM_X);
    cudaFuncSetAttribute(mdlstm_mma,
                         cudaFuncAttributeMaxDynamicSharedMemorySize, SMEM_P);

    cvt_x<<<(Bk * 256 * WH) / 256, 256>>>(x);
    cvt_w<<<(256 * 1280) / 256, 256>>>(Wx);
    xp_tc<<<dim3(MXP / 64, Gg / 128), 256, SMEM_X>>>(bias);
    mdlstm_mma<<<NBLK, 256, SMEM_P>>>(Wh1, Wh2);
    bn_reduce1<<<64, 256>>>();
    bn_reduce2<<<1, 256>>>(gamma, beta);
    writeout<<<Bk * Wd, 256>>>(out);
}

// round 17
// speedup vs baseline: 1.2601x; 1.1364x over previous
#include <cuda_runtime.h>
#include <cuda_bf16.h>
#include <math.h>

#define Bk   8
#define Cc   512
#define Wd   64
#define Hd   32
#define HIDd 256
#define Gg   1280
#define WH   (Wd*Hd)        // 2048
#define MXP  (Bk*WH)        // 16384
#define NDIAG (Wd + Hd - 1) // 95
#define NBLK 144
#define RG   9

// ---- persistent-kernel smem layout (bytes), pitch 1040 (mod128=16 -> ldmatrix conflict-free) ----
#define PIT    1040
#define WBH_O  0                     // weights hi: 80 rows
#define WBL_O  (80*PIT)              // 83200
#define ABH_O  (2*80*PIT)            // 166400, A hi: 30 rows
#define ABL_O  (ABH_O + 30*PIT)      // 197600
#define ZR_O   (ABL_O + 30*PIT)      // 228800, shared zero row
#define SMEM_P (ZR_O + PIT + 48)     // 229888

// ---- xp_tc smem layout (bytes): A 64x128B, B 128x128B, hi/lo each ----
#define XA_HI 0
#define XA_LO 8192
#define XB_HI 16384
#define XB_LO 32768
#define SMEM_X 49152

// ---------------- device scratch ----------------
__device__ float g_xp[(size_t)MXP * Gg];
__device__ float g_h [(size_t)WH * Bk * HIDd];
__device__ float g_c [(size_t)WH * Bk * HIDd];
__device__ unsigned g_hh2[(size_t)WH * Bk * 128];   // h as bf16-hi k-pairs
__device__ unsigned g_hl2[(size_t)WH * Bk * 128];   // h as bf16-lo k-pairs
__device__ unsigned g_x2h[(size_t)Bk * 256 * WH];   // x packed [b][kp][wh]
__device__ unsigned g_x2l[(size_t)Bk * 256 * WH];
__device__ unsigned g_w2h[1280 * 256];              // Wx packed [n][kp]
__device__ unsigned g_w2l[1280 * 256];
__device__ float g_part[2 * 64 * HIDd];
__device__ float g_scale[HIDd];
__device__ float g_shift[HIDd];
__device__ unsigned g_cnt = 0;
__device__ unsigned g_gen = 0;

// ---------------- helpers ----------------
__device__ __forceinline__ unsigned smem_u32(const void* p) {
    unsigned a;
    asm("{ .reg .u64 t; cvta.to.shared.u64 t, %1; cvt.u32.u64 %0, t; }" : "=r"(a) : "l"(p));
    return a;
}
__device__ __forceinline__ unsigned pk(__nv_bfloat16 a, __nv_bfloat16 b) {
    __nv_bfloat162 t; t.x = a; t.y = b;
    return *(unsigned*)&t;
}
__device__ __forceinline__ void split_bf16(float f, __nv_bfloat16& h, __nv_bfloat16& l) {
    h = __float2bfloat16(f);
    l = __float2bfloat16(f - __bfloat162float(h));
}
// XOR-swizzled frag load, 128B row pitch (xp kernel)
__device__ __forceinline__ unsigned ldfrag32(const unsigned* base, int r, int k) {
    unsigned boff = ((unsigned)(k * 2)) ^ (((unsigned)r & 7u) << 4);
    return base[(r << 5) + (boff >> 2)];
}
__device__ __forceinline__ void mma_bf16(float* d, unsigned a0, unsigned a1,
                                         unsigned a2, unsigned a3,
                                         unsigned b0, unsigned b1) {
    asm volatile(
        "mma.sync.aligned.m16n8k16.row.col.f32.bf16.bf16.f32 "
        "{%0,%1,%2,%3}, {%4,%5,%6,%7}, {%8,%9}, {%0,%1,%2,%3};"
        : "+f"(d[0]), "+f"(d[1]), "+f"(d[2]), "+f"(d[3])
        : "r"(a0), "r"(a1), "r"(a2), "r"(a3), "r"(b0), "r"(b1));
}
__device__ __forceinline__ void ldm_x4(unsigned* r, unsigned addr) {
    asm volatile("ldmatrix.sync.aligned.m8n8.x4.shared.b16 {%0,%1,%2,%3}, [%4];"
                 : "=r"(r[0]), "=r"(r[1]), "=r"(r[2]), "=r"(r[3]) : "r"(addr));
}
__device__ __forceinline__ void ldm_x2(unsigned* r, unsigned addr) {
    asm volatile("ldmatrix.sync.aligned.m8n8.x2.shared.b16 {%0,%1}, [%2];"
                 : "=r"(r[0]), "=r"(r[1]) : "r"(addr));
}

// ---------------- pre-pack kernels ----------------
__global__ __launch_bounds__(256) void cvt_x(const float* __restrict__ x) {
    size_t i = (size_t)blockIdx.x * 256 + threadIdx.x;
    int wh = (int)(i & 2047);
    int kp = (int)((i >> 11) & 255);
    int b  = (int)(i >> 19);
    float f0 = x[((size_t)b * Cc + 2 * kp) * WH + wh];
    float f1 = x[((size_t)b * Cc + 2 * kp + 1) * WH + wh];
    __nv_bfloat16 h0, l0, h1, l1;
    split_bf16(f0, h0, l0);
    split_bf16(f1, h1, l1);
    g_x2h[i] = pk(h0, h1);
    g_x2l[i] = pk(l0, l1);
}

__global__ __launch_bounds__(256) void cvt_w(const float* __restrict__ Wx) {
    int i = blockIdx.x * 256 + threadIdx.x;
    int n  = i % 1280;
    int kp = i / 1280;
    float f0 = Wx[(size_t)(2 * kp) * Gg + n];
    float f1 = Wx[(size_t)(2 * kp + 1) * Gg + n];
    __nv_bfloat16 h0, l0, h1, l1;
    split_bf16(f0, h0, l0);
    split_bf16(f1, h1, l1);
    g_w2h[n * 256 + kp] = pk(h0, h1);
    g_w2l[n * 256 + kp] = pk(l0, l1);
}

// ---------------- Kernel A: xp = x @ Wx + b on HMMA (pre-packed, proven R14) ----------------
__global__ __launch_bounds__(256) void xp_tc(const float* __restrict__ bias) {
    extern __shared__ unsigned char smx[];
    const int tid = threadIdx.x;
    const int lane = tid & 31;
    const int wid  = tid >> 5;
    const int gid  = lane >> 2;
    const int tq   = lane & 3;

    const int m0 = blockIdx.x * 64;
    const int n0 = blockIdx.y * 128;
    const int b   = m0 >> 11;
    const int wh0 = m0 & 2047;

    const int wm = (wid & 3) * 16;
    const int nh = wid >> 2;

    const unsigned* AH = (const unsigned*)(smx + XA_HI);
    const unsigned* AL = (const unsigned*)(smx + XA_LO);
    const unsigned* BH = (const unsigned*)(smx + XB_HI);
    const unsigned* BL = (const unsigned*)(smx + XB_LO);

    const int a_kpl = tid >> 3;
    const int a_m4  = (tid & 7) * 8;
    const int b_n   = tid >> 1;
    const int b_hf  = tid & 1;

    float dd[8][4];
#pragma unroll
    for (int j = 0; j < 8; j++)
#pragma unroll
        for (int e = 0; e < 4; e++) dd[j][e] = 0.f;

    for (int c = 0; c < 8; c++) {
        __syncthreads();
        {
            const unsigned* sh = g_x2h + ((size_t)(b * 256 + c * 32 + a_kpl)) * WH + wh0 + a_m4;
            const unsigned* sl = g_x2l + ((size_t)(b * 256 + c * 32 + a_kpl)) * WH + wh0 + a_m4;
            uint4 h0 = *(const uint4*)sh;
            uint4 h1 = *(const uint4*)(sh + 4);
            uint4 l0 = *(const uint4*)sl;
            uint4 l1 = *(const uint4*)(sl + 4);
            unsigned hv[8] = {h0.x, h0.y, h0.z, h0.w, h1.x, h1.y, h1.z, h1.w};
            unsigned lv[8] = {l0.x, l0.y, l0.z, l0.w, l1.x, l1.y, l1.z, l1.w};
#pragma unroll
            for (int e = 0; e < 8; e++) {
                int r = a_m4 + e;
                unsigned boff = ((unsigned)(4 * a_kpl)) ^ (((unsigned)r & 7u) << 4);
                *(unsigned*)(smx + XA_HI + r * 128 + boff) = hv[e];
                *(unsigned*)(smx + XA_LO + r * 128 + boff) = lv[e];
            }
        }
        {
            const unsigned* sh = g_w2h + (size_t)(n0 + b_n) * 256 + c * 32 + b_hf * 16;
            const unsigned* sl = g_w2l + (size_t)(n0 + b_n) * 256 + c * 32 + b_hf * 16;
#pragma unroll
            for (int q = 0; q < 4; q++) {
                uint4 hq = *(const uint4*)(sh + q * 4);
                uint4 lq = *(const uint4*)(sl + q * 4);
                unsigned hv[4] = {hq.x, hq.y, hq.z, hq.w};
                unsigned lv[4] = {lq.x, lq.y, lq.z, lq.w};
#pragma unroll
                for (int e = 0; e < 4; e++) {
                    int kpl = b_hf * 16 + q * 4 + e;
                    unsigned boff = ((unsigned)(4 * kpl)) ^ (((unsigned)b_n & 7u) << 4);
                    *(unsigned*)(smx + XB_HI + b_n * 128 + boff) = hv[e];
                    *(unsigned*)(smx + XB_LO + b_n * 128 + boff) = lv[e];
                }
            }
        }
        __syncthreads();

        const int ra = wm + gid;
#pragma unroll
        for (int s = 0; s < 4; s++) {
            int ka = s * 16 + tq * 2;
            unsigned ah0 = ldfrag32(AH, ra,     ka);
            unsigned ah1 = ldfrag32(AH, ra + 8, ka);
            unsigned ah2 = ldfrag32(AH, ra,     ka + 8);
            unsigned ah3 = ldfrag32(AH, ra + 8, ka + 8);
            unsigned al0 = ldfrag32(AL, ra,     ka);
            unsigned al1 = ldfrag32(AL, ra + 8, ka);
            unsigned al2 = ldfrag32(AL, ra,     ka + 8);
            unsigned al3 = ldfrag32(AL, ra + 8, ka + 8);
#pragma unroll
            for (int j = 0; j < 8; j++) {
                int nr = (nh * 8 + j) * 8 + gid;
                unsigned bh0 = ldfrag32(BH, nr, ka);
                unsigned bh1 = ldfrag32(BH, nr, ka + 8);
                unsigned bl0 = ldfrag32(BL, nr, ka);
                unsigned bl1 = ldfrag32(BL, nr, ka + 8);
                mma_bf16(dd[j], ah0, ah1, ah2, ah3, bh0, bh1);
                mma_bf16(dd[j], ah0, ah1, ah2, ah3, bl0, bl1);
                mma_bf16(dd[j], al0, al1, al2, al3, bh0, bh1);
            }
        }
    }

#pragma unroll
    for (int j = 0; j < 8; j++) {
        int col = n0 + (nh * 8 + j) * 8 + tq * 2;
        float b0 = bias[col];
        float b1 = bias[col + 1];
        int mA = m0 + wm + gid;
        int mB = mA + 8;
        *(float2*)&g_xp[(size_t)mA * Gg + col] = make_float2(dd[j][0] + b0, dd[j][1] + b1);
        *(float2*)&g_xp[(size_t)mB * Gg + col] = make_float2(dd[j][2] + b0, dd[j][3] + b1);
    }
}

// ---------------- grid-wide software barrier ----------------
__device__ __forceinline__ void gsync() {
    __threadfence();
    __syncthreads();
    if (threadIdx.x == 0) {
        unsigned old = *(volatile unsigned*)&g_gen;
        if (atomicAdd(&g_cnt, 1u) == NBLK - 1) {
            g_cnt = 0;
            __threadfence();
            *(volatile unsigned*)&g_gen = old + 1;
        } else {
            while (*(volatile unsigned*)&g_gen == old) { }
        }
        __threadfence();
    }
    __syncthreads();
}

// ---------------- persistent MD-LSTM recurrence: ldmatrix + padded pitch ----------------
// Block: nb = bid&15 (16 hid cols = 80 gate cols), rg = bid>>4 (9 row groups).
// Weights hi/lo [80 rows][512 k] bf16 pitch 1040; A hi/lo [30 rows][512 k] pitch 1040.
// Rows 30/31 of the mma tile map to a shared zero row.
// mt2>16: 2 m-strips, warp = (strip = wid&1, tiles {wg, wg+4, wg+8}).
// mt2<=16: 1 m-strip, warp tiles {wid, wid+8}.
__global__ __launch_bounds__(256, 1) void mdlstm_mma(const float* __restrict__ Wh1,
                                                     const float* __restrict__ Wh2) {
    extern __shared__ unsigned char smb[];
    const unsigned sb = smem_u32(smb);

    const int tid = threadIdx.x;
    const int bid = blockIdx.x;
    const int nb  = bid & 15;
    const int rg  = bid >> 4;

    // one-time weight preload into padded layout
    for (int i = tid; i < 80 * 512; i += 256) {
        int c = i >> 9, k = i & 511;
        int gc = (c >> 4) * 256 + nb * 16 + (c & 15);
        float w = (k < 256) ? Wh1[(size_t)k * Gg + gc]
                            : Wh2[(size_t)(k - 256) * Gg + gc];
        __nv_bfloat16 h, l;
        split_bf16(w, h, l);
        *(__nv_bfloat16*)(smb + WBH_O + c * PIT + k * 2) = h;
        *(__nv_bfloat16*)(smb + WBL_O + c * PIT + k * 2) = l;
    }
    // zero row
    for (int i = tid; i < PIT / 4; i += 256)
        *(unsigned*)(smb + ZR_O + i * 4) = 0;

    const int lane = tid & 31;
    const int wid  = tid >> 5;
    const int gid  = lane >> 2;
    const int tq   = lane & 3;
    const int srow = tid >> 3;         // staging row 0..31 (rows >=30 idle)
    const int sq   = tid & 7;

    // B ldmatrix lane geometry (constant)
    const int b_lrow = lane & 7;
    const int b_koff = ((lane >> 3) & 1) * 16;
    // A ldmatrix lane geometry (strip-dependent row base added later)
    const int a_lrow = ((lane >> 3) & 1) * 8 + (lane & 7);
    const int a_koff = (lane >> 4) * 16;

    for (int d = 0; d < NDIAG; d++) {
        int w_lo = d - (Hd - 1); if (w_lo < 0) w_lo = 0;
        int w_hi = (d < Wd - 1) ? d : (Wd - 1);
        int M = (w_hi - w_lo + 1) * Bk;
        int mt2 = (M + RG - 1) / RG;   // <=29
        int r0 = rg * mt2;

        if (r0 < M) {
            // ---- schedule ----
            int wm, nn = 0;
            int tlist[3] = {0, 0, 0};
            if (mt2 > 16) {
                wm = (wid & 1) * 16;
                int wg = wid >> 1;
                for (int t = wg; t < 10; t += 4) tlist[nn++] = t;
            } else {
                wm = 0;
                for (int t = wid; t < 10; t += 8) tlist[nn++] = t;
            }

            // ---- operand addresses (linear in k) ----
            int arow = wm + a_lrow;
            unsigned aH = (arow < 30) ? (sb + ABH_O + arow * PIT + a_koff)
                                      : (sb + ZR_O + a_koff);
            unsigned aL = (arow < 30) ? (sb + ABL_O + arow * PIT + a_koff)
                                      : (sb + ZR_O + a_koff);
            unsigned bHa[3], bLa[3];
#pragma unroll
            for (int j = 0; j < 3; j++) {
                int t = tlist[j];
                int brow = t * 8 + b_lrow;
                bHa[j] = sb + WBH_O + brow * PIT + b_koff;
                bLa[j] = sb + WBL_O + brow * PIT + b_koff;
            }

            // ---- stage A from pre-packed bf16 h (pure copies) ----
            if (srow < 30) {
                const unsigned* plh = nullptr; const unsigned* pll = nullptr;
                const unsigned* puh = nullptr; const unsigned* pul = nullptr;
                int gr = r0 + srow;
                if (srow < mt2 && gr < M) {
                    int ci = gr >> 3, b = gr & 7;
                    int w = w_lo + ci, h = d - w;
                    if (h > 0) {
                        size_t cell = (size_t)((w * Hd + (h - 1)) * Bk + b);
                        plh = g_hh2 + cell * 128;
                        pll = g_hl2 + cell * 128;
                    }
                    if (w > 0) {
                        size_t cell = (size_t)(((w - 1) * Hd + h) * Bk + b);
                        puh = g_hh2 + cell * 128;
                        pul = g_hl2 + cell * 128;
                    }
                }
#pragma unroll
                for (int j = 0; j < 8; j++) {
                    int kk = (sq + 8 * j) * 8;
                    uint4 Hv = make_uint4(0, 0, 0, 0);
                    uint4 Lv = make_uint4(0, 0, 0, 0);
                    if (j < 4) {
                        if (plh) { int kp0 = kk >> 1;
                            Hv = *(const uint4*)(plh + kp0);
                            Lv = *(const uint4*)(pll + kp0); }
                    } else {
                        if (puh) { int kp0 = (kk - 256) >> 1;
                            Hv = *(const uint4*)(puh + kp0);
                            Lv = *(const uint4*)(pul + kp0); }
                    }
                    *(uint4*)(smb + ABH_O + srow * PIT + kk * 2) = Hv;
                    *(uint4*)(smb + ABL_O + srow * PIT + kk * 2) = Lv;
                }
            }
            __syncthreads();

            // ---- mma over full K: 32 k16 steps, ldmatrix frags ----
            float dd[3][4];
#pragma unroll
            for (int j = 0; j < 3; j++)
#pragma unroll
                for (int e = 0; e < 4; e++) dd[j][e] = 0.f;

#pragma unroll 4
            for (int s = 0; s < 32; s++) {
                unsigned ah[4], al[4];
                ldm_x4(ah, aH); aH += 32;
                ldm_x4(al, aL); aL += 32;
#pragma unroll
                for (int j = 0; j < 3; j++) {
                    if (j < nn) {
                        unsigned bh[2], bl[2];
                        ldm_x2(bh, bHa[j]);
                        ldm_x2(bl, bLa[j]);
                        mma_bf16(dd[j], ah[0], ah[1], ah[2], ah[3], bh[0], bh[1]);
                        mma_bf16(dd[j], ah[0], ah[1], ah[2], ah[3], bl[0], bl[1]);
                        mma_bf16(dd[j], al[0], al[1], al[2], al[3], bh[0], bh[1]);
                    }
                    bHa[j] += 32;
                    bLa[j] += 32;
                }
            }

            // ---- gather D frags to smem (overlay on A-hi region) ----
            __syncthreads();
            float* Gs = (float*)(smb + ABH_O);   // [32][84]
#pragma unroll
            for (int j = 0; j < 3; j++) {
                if (j < nn) {
                    int c0 = tlist[j] * 8 + tq * 2;
                    *(float2*)&Gs[(wm + gid) * 84 + c0]     = make_float2(dd[j][0], dd[j][1]);
                    *(float2*)&Gs[(wm + gid + 8) * 84 + c0] = make_float2(dd[j][2], dd[j][3]);
                }
            }
            __syncthreads();

            // ---- fused LSTM pointwise + bf16 h pair emit ----
#pragma unroll
            for (int pass = 0; pass < 2; pass++) {
                int r = (tid >> 4) + pass * 16;
                int hidx = tid & 15;
                float hv = 0.f;
                bool valid = false;
                int w = 0, h = 0, b = 0;
                if (r < mt2) {
                    int gr = r0 + r;
                    if (gr < M) {
                        int ci = gr >> 3; b = gr & 7;
                        w = w_lo + ci; h = d - w;
                        valid = true;
                        const int hid = nb * 16 + hidx;

                        const float* xg = g_xp + ((size_t)(b * WH + w * Hd + h)) * Gg;
                        float gi  = Gs[r * 84 +   0 + hidx] + xg[hid];
                        float gf1 = Gs[r * 84 +  16 + hidx] + xg[HIDd + hid];
                        float gf2 = Gs[r * 84 +  32 + hidx] + xg[2 * HIDd + hid];
                        float go  = Gs[r * 84 +  48 + hidx] + xg[3 * HIDd + hid];
                        float gc  = Gs[r * 84 +  64 + hidx] + xg[4 * HIDd + hid];

                        float i_ = 1.f / (1.f + expf(-gi));
                        float f1 = 1.f / (1.f + expf(-gf1));
                        float f2 = 1.f / (1.f + expf(-gf2));
                        float o_ = 1.f / (1.f + expf(-go));
                        float cand = tanhf(gc);

                        float cl = (h > 0) ? g_c[((size_t)((w * Hd + (h - 1)) * Bk + b)) * HIDd + hid] : 0.f;
                        float cu = (w > 0) ? g_c[((size_t)(((w - 1) * Hd + h) * Bk + b)) * HIDd + hid] : 0.f;

                        float cc = i_ * cand + f1 * cl + f2 * cu;
                        hv = o_ * tanhf(cc);

                        size_t oidx = ((size_t)((w * Hd + h) * Bk + b)) * HIDd + hid;
                        g_c[oidx] = cc;
                        g_h[oidx] = hv;
                    }
                }
                float hv_n = __shfl_down_sync(0xffffffffu, hv, 1);
                if (valid && !(hidx & 1)) {
                    __nv_bfloat16 h0, l0, h1, l1;
                    split_bf16(hv, h0, l0);
                    split_bf16(hv_n, h1, l1);
                    size_t cell = (size_t)((w * Hd + h) * Bk + b);
                    int kp = nb * 8 + (hidx >> 1);
                    g_hh2[cell * 128 + kp] = pk(h0, h1);
                    g_hl2[cell * 128 + kp] = pk(l0, l1);
                }
            }
        }

        gsync();
    }
}

// ---------------- BN stats ----------------
__global__ __launch_bounds__(256) void bn_reduce1() {
    const int t = threadIdx.x;
    const size_t r0 = (size_t)blockIdx.x * 256;
    float s = 0.f, s2 = 0.f;
    for (int r = 0; r < 256; r++) {
        float v = g_h[(r0 + r) * HIDd + t];
        s += v;
        s2 += v * v;
    }
    g_part[blockIdx.x * HIDd + t] = s;
    g_part[64 * HIDd + blockIdx.x * HIDd + t] = s2;
}

__global__ __launch_bounds__(256) void bn_reduce2(const float* __restrict__ gamma,
                                                  const float* __restrict__ beta) {
    const int t = threadIdx.x;
    float s0 = 0.f, s1 = 0.f, q0 = 0.f, q1 = 0.f;
#pragma unroll 4
    for (int i = 0; i < 64; i += 2) {
        s0 += g_part[i * HIDd + t];
        s1 += g_part[(i + 1) * HIDd + t];
        q0 += g_part[64 * HIDd + i * HIDd + t];
        q1 += g_part[64 * HIDd + (i + 1) * HIDd + t];
    }
    float s = s0 + s1, s2 = q0 + q1;
    const float invn = 1.f / (float)MXP;
    float mean = s * invn;
    float var  = s2 * invn - mean * mean;
    float sc   = gamma[t] * rsqrtf(var + 1e-5f);
    g_scale[t] = sc;
    g_shift[t] = beta[t] - mean * sc;
}

// ---------------- final writeout ----------------
__global__ __launch_bounds__(256) void writeout(float* __restrict__ out) {
    __shared__ float t[32][257];
    const int bw = blockIdx.x;
    const int b  = bw >> 6;
    const int w  = bw & 63;
    const int tid = threadIdx.x;
    const int ch8 = tid >> 5;
    const int hl  = tid & 31;

    for (int hh = 0; hh < 32; hh++)
        t[hh][tid] = g_h[((size_t)((w * Hd + hh) * Bk + b)) * HIDd + tid];
    __syncthreads();
    for (int c0 = 0; c0 < 256; c0 += 8) {
        int ch = c0 + ch8;
        float v = t[hl][ch];
        size_t oi = (((size_t)b * HIDd + ch) * Wd + w) * Hd + hl;
        out[oi] = tanhf(v * g_scale[ch] + g_shift[ch]);
        out[(size_t)MXP * HIDd + oi] = v;
    }
    __syncthreads();

    for (int hh = 0; hh < 32; hh++)
        t[hh][tid] = g_c[((size_t)((w * Hd + hh) * Bk + b)) * HIDd + tid];
    __syncthreads();
    for (int c0 = 0; c0 < 256; c0 += 8) {
        int ch = c0 + ch8;
        size_t oi = (((size_t)b * HIDd + ch) * Wd + w) * Hd + hl;
        out[(size_t)2 * MXP * HIDd + oi] = t[hl][ch];
    }
}

// ---------------- launch ----------------
extern "C" void kernel_launch(void* const* d_in, const int* in_sizes, int n_in,
                              void* d_out, int out_size) {
    const float* x     = (const float*)d_in[0];
    const float* Wx    = (const float*)d_in[1];
    const float* Wh1   = (const float*)d_in[2];
    const float* Wh2   = (const float*)d_in[3];
    const float* bias  = (const float*)d_in[4];
    const float* gamma = (const float*)d_in[5];
    const float* beta  = (const float*)d_in[6];
    float* out = (float*)d_out;

    cudaFuncSetAttribute(xp_tc,
                         cudaFuncAttributeMaxDynamicSharedMemorySize, SMEM_X);
    cudaFuncSetAttribute(mdlstm_mma,
                         cudaFuncAttributeMaxDynamicSharedMemorySize, SMEM_P);

    cvt_x<<<(Bk * 256 * WH) / 256, 256>>>(x);
    cvt_w<<<(256 * 1280) / 256, 256>>>(Wx);
    xp_tc<<<dim3(MXP / 64, Gg / 128), 256, SMEM_X>>>(bias);
    mdlstm_mma<<<NBLK, 256, SMEM_P>>>(Wh1, Wh2);
    bn_reduce1<<<64, 256>>>();
    bn_reduce2<<<1, 256>>>(gamma, beta);
    writeout<<<Bk * Wd, 256>>>(out);
}